// round 6
// baseline (speedup 1.0000x reference)
#include <cuda_runtime.h>
#include <cuda_bf16.h>
#include <math_constants.h>
#include <cstdint>

#define DIMC     384
#define NHEADS   12
#define HD       32
#define NTOK     49
#define NWIN     4096
#define MROWS    (NWIN * NTOK)   // 200704
#define QKV_N    (3 * DIMC)      // 1152
#define KDIM     384

// Scratch (device globals — no allocation allowed)
__device__ float         g_qkv[(size_t)MROWS * QKV_N];
__device__ __nv_bfloat16 g_xh [(size_t)MROWS * DIMC];
__device__ __nv_bfloat16 g_xl [(size_t)MROWS * DIMC];
__device__ __nv_bfloat16 g_ah [(size_t)MROWS * DIMC];
__device__ __nv_bfloat16 g_al [(size_t)MROWS * DIMC];
__device__ __nv_bfloat16 g_qwh[(size_t)KDIM * QKV_N];
__device__ __nv_bfloat16 g_qwl[(size_t)KDIM * QKV_N];
__device__ __nv_bfloat16 g_pwh[(size_t)KDIM * DIMC];
__device__ __nv_bfloat16 g_pwl[(size_t)KDIM * DIMC];

// ---------------------------------------------------------------------------
__device__ __forceinline__ void split1(float x, __nv_bfloat16& h, __nv_bfloat16& l) {
    h = __float2bfloat16(x);
    l = __float2bfloat16(x - __bfloat162float(h));
}
__device__ __forceinline__ void split2(float x0, float x1,
                                       __nv_bfloat162& h, __nv_bfloat162& l) {
    __nv_bfloat16 h0, l0, h1, l1;
    split1(x0, h0, l0);
    split1(x1, h1, l1);
    h = __nv_bfloat162(h0, h1);
    l = __nv_bfloat162(l0, l1);
}

__global__ void __launch_bounds__(256)
split_f32(const float* __restrict__ in, __nv_bfloat16* __restrict__ hi,
          __nv_bfloat16* __restrict__ lo, size_t n4)
{
    size_t i = (size_t)blockIdx.x * blockDim.x + threadIdx.x;
    if (i >= n4) return;
    float4 v = ((const float4*)in)[i];
    __nv_bfloat162 h0, l0, h1, l1;
    split2(v.x, v.y, h0, l0);
    split2(v.z, v.w, h1, l1);
    ((__nv_bfloat162*)hi)[i * 2]     = h0;
    ((__nv_bfloat162*)hi)[i * 2 + 1] = h1;
    ((__nv_bfloat162*)lo)[i * 2]     = l0;
    ((__nv_bfloat162*)lo)[i * 2 + 1] = l1;
}

// ---------------------------------------------------------------------------
// Tensor-core GEMM, bf16x3 (hh+hl+lh), 3-stage cp.async.
// BM=256, BN=128, BK=32, 256 threads = 8 warps as 4(m) x 2(n), warp tile 64x64.
// Larger warp tile cuts redundant smem fragment reads ~1.6x vs 64x32 warps.
// ---------------------------------------------------------------------------
#define AST 40     // A smem row stride (bf16)
#define BST 136    // B smem row stride (bf16)
#define SA_ELEMS (256 * AST)                       // 10240
#define SB_ELEMS (32 * BST)                        // 4352
#define STAGE_ELEMS (2 * SA_ELEMS + 2 * SB_ELEMS)  // 29184 elems (58368 B)
#define NSTAGE 3
#define GEMM_SMEM (NSTAGE * STAGE_ELEMS * 2)       // 175104 bytes

__device__ __forceinline__ uint32_t smem_u32(const void* p) {
    return (uint32_t)__cvta_generic_to_shared(p);
}
__device__ __forceinline__ void cp16(uint32_t dst, const void* src) {
    asm volatile("cp.async.cg.shared.global [%0], [%1], 16;" :: "r"(dst), "l"(src));
}
__device__ __forceinline__ void cp_commit() { asm volatile("cp.async.commit_group;"); }
__device__ __forceinline__ void cp_wait0()  { asm volatile("cp.async.wait_group 0;"); }
__device__ __forceinline__ void cp_wait1()  { asm volatile("cp.async.wait_group 1;"); }

__device__ __forceinline__ void ldsm_x4(unsigned* r, const void* p) {
    unsigned a = smem_u32(p);
    asm volatile("ldmatrix.sync.aligned.m8n8.x4.shared.b16 {%0,%1,%2,%3}, [%4];"
        : "=r"(r[0]), "=r"(r[1]), "=r"(r[2]), "=r"(r[3]) : "r"(a));
}
__device__ __forceinline__ void ldsm_x4_t(unsigned* r, const void* p) {
    unsigned a = smem_u32(p);
    asm volatile("ldmatrix.sync.aligned.m8n8.x4.trans.shared.b16 {%0,%1,%2,%3}, [%4];"
        : "=r"(r[0]), "=r"(r[1]), "=r"(r[2]), "=r"(r[3]) : "r"(a));
}
__device__ __forceinline__ void mma_bf16(float* d, const unsigned* a, const unsigned* b) {
    asm volatile(
        "mma.sync.aligned.m16n8k16.row.col.f32.bf16.bf16.f32 "
        "{%0,%1,%2,%3}, {%4,%5,%6,%7}, {%8,%9}, {%0,%1,%2,%3};"
        : "+f"(d[0]), "+f"(d[1]), "+f"(d[2]), "+f"(d[3])
        : "r"(a[0]), "r"(a[1]), "r"(a[2]), "r"(a[3]), "r"(b[0]), "r"(b[1]));
}

__global__ void __launch_bounds__(256, 1)
gemm_bf16x3(const __nv_bfloat16* __restrict__ Ah, const __nv_bfloat16* __restrict__ Al,
            const __nv_bfloat16* __restrict__ Bh, const __nv_bfloat16* __restrict__ Bl,
            const float* __restrict__ bias, float* __restrict__ C,
            int M, int N, int K)
{
    extern __shared__ __nv_bfloat16 smem[];

    const int bm = blockIdx.y * 256;
    const int bn = blockIdx.x * 128;
    const int tid  = threadIdx.x;
    const int warp = tid >> 5;
    const int lane = tid & 31;
    const int wm = (warp >> 1) * 64;   // 0/64/128/192
    const int wn = (warp & 1)  * 64;   // 0/64

    // global->smem load mapping (16B chunks)
    const int arow = tid;               // A row 0..255
    const int brow = tid >> 3;          // B row 0..31
    const int bc0  = (tid & 7) * 8;     // B col chunk (bf16), +64

    float acc[4][8][4] = {};

    auto issue = [&](int kt, int stage) {
        __nv_bfloat16* dAh = smem + stage * STAGE_ELEMS;
        __nv_bfloat16* dAl = dAh + SA_ELEMS;
        const size_t gA = (size_t)(bm + arow) * K + kt;
        #pragma unroll
        for (int j = 0; j < 4; j++) {
            cp16(smem_u32(&dAh[arow * AST + j * 8]), Ah + gA + j * 8);
            cp16(smem_u32(&dAl[arow * AST + j * 8]), Al + gA + j * 8);
        }
        __nv_bfloat16* dBh = dAl + SA_ELEMS;
        __nv_bfloat16* dBl = dBh + SB_ELEMS;
        const size_t gB = (size_t)(kt + brow) * N + bn;
        #pragma unroll
        for (int j = 0; j < 2; j++) {
            const int c = bc0 + j * 64;
            cp16(smem_u32(&dBh[brow * BST + c]), Bh + gB + c);
            cp16(smem_u32(&dBl[brow * BST + c]), Bl + gB + c);
        }
    };

    const int nk = K / 32;   // 12
    issue(0, 0); cp_commit();
    issue(32, 1); cp_commit();

    #pragma unroll 1
    for (int it = 0; it < nk; it++) {
        const int cur = it % NSTAGE;

        if (it + 2 < nk) cp_wait1(); else cp_wait0();
        __syncthreads();
        if (it + 2 < nk) {
            issue((it + 2) * 32, (it + 2) % NSTAGE);
            cp_commit();
        }

        const __nv_bfloat16* pAh = smem + cur * STAGE_ELEMS;
        const __nv_bfloat16* pAl = pAh + SA_ELEMS;
        const __nv_bfloat16* pBh = pAl + SA_ELEMS;
        const __nv_bfloat16* pBl = pBh + SB_ELEMS;

        #pragma unroll
        for (int ks = 0; ks < 32; ks += 16) {
            unsigned af[4][4];               // A-hi, later overwritten with A-lo
            unsigned bh[4][4], bl[4][4];
            const int ar  = lane & 15;
            const int akc = ks + ((lane >> 4) << 3);
            const int bkr = ks + (lane & 15);
            const int bcc = ((lane >> 4) << 3);

            #pragma unroll
            for (int mi = 0; mi < 4; mi++)
                ldsm_x4(af[mi], &pAh[(wm + mi * 16 + ar) * AST + akc]);
            #pragma unroll
            for (int nb = 0; nb < 4; nb++)
                ldsm_x4_t(bh[nb], &pBh[bkr * BST + wn + nb * 16 + bcc]);
            #pragma unroll
            for (int nb = 0; nb < 4; nb++)
                ldsm_x4_t(bl[nb], &pBl[bkr * BST + wn + nb * 16 + bcc]);

            // hh + hl
            #pragma unroll
            for (int mi = 0; mi < 4; mi++)
                #pragma unroll
                for (int ni = 0; ni < 8; ni++) {
                    mma_bf16(acc[mi][ni], af[mi], &bh[ni >> 1][(ni & 1) * 2]);
                    mma_bf16(acc[mi][ni], af[mi], &bl[ni >> 1][(ni & 1) * 2]);
                }
            // lh
            #pragma unroll
            for (int mi = 0; mi < 4; mi++)
                ldsm_x4(af[mi], &pAl[(wm + mi * 16 + ar) * AST + akc]);
            #pragma unroll
            for (int mi = 0; mi < 4; mi++)
                #pragma unroll
                for (int ni = 0; ni < 8; ni++)
                    mma_bf16(acc[mi][ni], af[mi], &bh[ni >> 1][(ni & 1) * 2]);
        }
        __syncthreads();
    }

    // Epilogue
    #pragma unroll
    for (int ni = 0; ni < 8; ni++) {
        const int col = bn + wn + ni * 8 + (lane & 3) * 2;
        const float bx = bias[col];
        const float by = bias[col + 1];
        #pragma unroll
        for (int mi = 0; mi < 4; mi++) {
            const int row = bm + wm + mi * 16 + (lane >> 2);
            float* a4 = acc[mi][ni];
            *(float2*)&C[(size_t)row * N + col] =
                make_float2(a4[0] + bx, a4[1] + by);
            *(float2*)&C[(size_t)(row + 8) * N + col] =
                make_float2(a4[2] + bx, a4[3] + by);
        }
    }
}

// ---------------------------------------------------------------------------
// Window attention: one block per (window, head). Emits bf16 hi/lo.
// ---------------------------------------------------------------------------
__global__ void __launch_bounds__(256)
win_attn(const float* __restrict__ qkv, const float* __restrict__ bias_table,
         const int* __restrict__ rpi,
         __nv_bfloat16* __restrict__ outh, __nv_bfloat16* __restrict__ outl)
{
    const int b = blockIdx.x;
    const int h = blockIdx.y;
    const int tid = threadIdx.x;

    __shared__ float qs[NTOK][HD + 1];
    __shared__ float ks[NTOK][HD + 1];
    __shared__ float vs[NTOK][HD + 1];
    __shared__ float at[NTOK][NTOK + 1];

    const float scale = 0.17677669529663687f;

    for (int idx = tid; idx < NTOK * HD; idx += 256) {
        const int n = idx >> 5, d = idx & 31;
        const size_t base = ((size_t)b * NTOK + n) * QKV_N + h * HD + d;
        qs[n][d] = qkv[base] * scale;
        ks[n][d] = qkv[base + DIMC];
        vs[n][d] = qkv[base + 2 * DIMC];
    }
    __syncthreads();

    for (int idx = tid; idx < NTOK * NTOK; idx += 256) {
        const int n = idx / NTOK, m = idx - n * NTOK;
        float s = 0.f;
        #pragma unroll
        for (int d = 0; d < HD; d++) s = fmaf(qs[n][d], ks[m][d], s);
        s += bias_table[rpi[idx] * NHEADS + h];
        at[n][m] = s;
    }
    __syncthreads();

    const int warp = tid >> 5, lane = tid & 31;
    for (int n = warp; n < NTOK; n += 8) {
        float v1 = at[n][lane];
        float v2 = (lane < NTOK - 32) ? at[n][lane + 32] : -CUDART_INF_F;
        float mx = fmaxf(v1, v2);
        #pragma unroll
        for (int o = 16; o; o >>= 1) mx = fmaxf(mx, __shfl_xor_sync(0xFFFFFFFFu, mx, o));
        float e1 = __expf(v1 - mx);
        float e2 = (lane < NTOK - 32) ? __expf(v2 - mx) : 0.f;
        float sm = e1 + e2;
        #pragma unroll
        for (int o = 16; o; o >>= 1) sm += __shfl_xor_sync(0xFFFFFFFFu, sm, o);
        const float inv = __frcp_rn(sm);
        at[n][lane] = e1 * inv;
        if (lane < NTOK - 32) at[n][lane + 32] = e2 * inv;
    }
    __syncthreads();

    for (int idx = tid; idx < NTOK * HD; idx += 256) {
        const int n = idx >> 5, d = idx & 31;
        float s = 0.f;
        #pragma unroll
        for (int m = 0; m < NTOK; m++) s = fmaf(at[n][m], vs[m][d], s);
        const size_t o = ((size_t)b * NTOK + n) * DIMC + h * HD + d;
        __nv_bfloat16 hv, lv;
        split1(s, hv, lv);
        outh[o] = hv;
        outl[o] = lv;
    }
}

// ---------------------------------------------------------------------------
extern "C" void kernel_launch(void* const* d_in, const int* in_sizes, int n_in,
                              void* d_out, int out_size)
{
    const float* x          = (const float*)d_in[0];
    const float* qkv_w      = (const float*)d_in[1];
    const float* qkv_b      = (const float*)d_in[2];
    const float* proj_w     = (const float*)d_in[3];
    const float* proj_b     = (const float*)d_in[4];
    const float* bias_table = (const float*)d_in[5];
    const int*   rpi        = (const int*)d_in[6];
    float* out = (float*)d_out;

    float *qkv;
    __nv_bfloat16 *xh, *xl, *ah, *al, *qwh, *qwl, *pwh, *pwl;
    cudaGetSymbolAddress((void**)&qkv, g_qkv);
    cudaGetSymbolAddress((void**)&xh, g_xh);
    cudaGetSymbolAddress((void**)&xl, g_xl);
    cudaGetSymbolAddress((void**)&ah, g_ah);
    cudaGetSymbolAddress((void**)&al, g_al);
    cudaGetSymbolAddress((void**)&qwh, g_qwh);
    cudaGetSymbolAddress((void**)&qwl, g_qwl);
    cudaGetSymbolAddress((void**)&pwh, g_pwh);
    cudaGetSymbolAddress((void**)&pwl, g_pwl);

    cudaFuncSetAttribute(gemm_bf16x3,
                         cudaFuncAttributeMaxDynamicSharedMemorySize, GEMM_SMEM);

    // 0) splits
    {
        size_t n4 = (size_t)MROWS * DIMC / 4;
        split_f32<<<(unsigned)((n4 + 255) / 256), 256>>>(x, xh, xl, n4);
        size_t w4 = (size_t)KDIM * QKV_N / 4;
        split_f32<<<(unsigned)((w4 + 255) / 256), 256>>>(qkv_w, qwh, qwl, w4);
        size_t p4 = (size_t)KDIM * DIMC / 4;
        split_f32<<<(unsigned)((p4 + 255) / 256), 256>>>(proj_w, pwh, pwl, p4);
    }
    // 1) QKV GEMM: [200704,384] x [384,1152] -> fp32
    {
        dim3 grid(QKV_N / 128, MROWS / 256);
        gemm_bf16x3<<<grid, 256, GEMM_SMEM>>>(xh, xl, qwh, qwl, qkv_b, qkv,
                                              MROWS, QKV_N, KDIM);
    }
    // 2) Window attention (emits bf16 hi/lo)
    {
        dim3 grid(NWIN, NHEADS);
        win_attn<<<grid, 256>>>(qkv, bias_table, rpi, ah, al);
    }
    // 3) Proj GEMM: [200704,384] x [384,384] -> out
    {
        dim3 grid(DIMC / 128, MROWS / 256);
        gemm_bf16x3<<<grid, 256, GEMM_SMEM>>>(ah, al, pwh, pwl, proj_b, out,
                                              MROWS, DIMC, KDIM);
    }
}

// round 7
// speedup vs baseline: 1.3617x; 1.3617x over previous
#include <cuda_runtime.h>
#include <cuda_bf16.h>
#include <math_constants.h>
#include <cstdint>

#define DIMC     384
#define NHEADS   12
#define HD       32
#define NTOK     49
#define NWIN     4096
#define MROWS    (NWIN * NTOK)   // 200704
#define QKV_N    (3 * DIMC)      // 1152
#define KDIM     384

// Scratch (device globals — no allocation allowed)
__device__ float         g_qkv[(size_t)MROWS * QKV_N];
__device__ __nv_bfloat16 g_xh [(size_t)MROWS * DIMC];
__device__ __nv_bfloat16 g_xl [(size_t)MROWS * DIMC];
__device__ __nv_bfloat16 g_ah [(size_t)MROWS * DIMC];
__device__ __nv_bfloat16 g_al [(size_t)MROWS * DIMC];
__device__ __nv_bfloat16 g_qwh[(size_t)KDIM * QKV_N];
__device__ __nv_bfloat16 g_qwl[(size_t)KDIM * QKV_N];
__device__ __nv_bfloat16 g_pwh[(size_t)KDIM * DIMC];
__device__ __nv_bfloat16 g_pwl[(size_t)KDIM * DIMC];
__device__ float         g_bias[NHEADS * NTOK * NTOK];   // expanded bias

// ---------------------------------------------------------------------------
__device__ __forceinline__ void split1(float x, __nv_bfloat16& h, __nv_bfloat16& l) {
    h = __float2bfloat16(x);
    l = __float2bfloat16(x - __bfloat162float(h));
}
__device__ __forceinline__ void split2(float x0, float x1,
                                       __nv_bfloat162& h, __nv_bfloat162& l) {
    __nv_bfloat16 h0, l0, h1, l1;
    split1(x0, h0, l0);
    split1(x1, h1, l1);
    h = __nv_bfloat162(h0, h1);
    l = __nv_bfloat162(l0, l1);
}

__global__ void __launch_bounds__(256)
split_f32(const float* __restrict__ in, __nv_bfloat16* __restrict__ hi,
          __nv_bfloat16* __restrict__ lo, size_t n4)
{
    size_t i = (size_t)blockIdx.x * blockDim.x + threadIdx.x;
    if (i >= n4) return;
    float4 v = ((const float4*)in)[i];
    __nv_bfloat162 h0, l0, h1, l1;
    split2(v.x, v.y, h0, l0);
    split2(v.z, v.w, h1, l1);
    ((__nv_bfloat162*)hi)[i * 2]     = h0;
    ((__nv_bfloat162*)hi)[i * 2 + 1] = h1;
    ((__nv_bfloat162*)lo)[i * 2]     = l0;
    ((__nv_bfloat162*)lo)[i * 2 + 1] = l1;
}

// Expand bias_table[rpi[nm]*12+h] -> g_bias[h][n][m]
__global__ void __launch_bounds__(256)
expand_bias(const float* __restrict__ bias_table, const int* __restrict__ rpi,
            float* __restrict__ out)
{
    int i = blockIdx.x * blockDim.x + threadIdx.x;   // h*2401 + nm
    if (i >= NHEADS * NTOK * NTOK) return;
    const int h = i / (NTOK * NTOK);
    const int nm = i - h * (NTOK * NTOK);
    out[i] = bias_table[rpi[nm] * NHEADS + h];
}

// ---------------------------------------------------------------------------
// Tensor-core GEMM, bf16x3 (hh+hl+lh), 3-stage cp.async, ONE sync per slab.
// BM=128, BN=128, BK=32, 256 threads (2x4 warps), warp tile 64x32, 2 CTAs/SM.
// ---------------------------------------------------------------------------
#define AST 40
#define BST 136
#define SA_ELEMS (128 * AST)                        // 5120
#define SB_ELEMS (32 * BST)                         // 4352
#define STAGE_ELEMS (2 * SA_ELEMS + 2 * SB_ELEMS)   // 18944 (37888 B)
#define NSTAGE 3
#define GEMM_SMEM (NSTAGE * STAGE_ELEMS * 2)        // 113664 bytes

__device__ __forceinline__ uint32_t smem_u32(const void* p) {
    return (uint32_t)__cvta_generic_to_shared(p);
}
__device__ __forceinline__ void cp16(uint32_t dst, const void* src) {
    asm volatile("cp.async.cg.shared.global [%0], [%1], 16;" :: "r"(dst), "l"(src));
}
__device__ __forceinline__ void cp_commit() { asm volatile("cp.async.commit_group;"); }
__device__ __forceinline__ void cp_wait0()  { asm volatile("cp.async.wait_group 0;"); }
__device__ __forceinline__ void cp_wait1()  { asm volatile("cp.async.wait_group 1;"); }

__device__ __forceinline__ void ldsm_x4(unsigned* r, const void* p) {
    unsigned a = smem_u32(p);
    asm volatile("ldmatrix.sync.aligned.m8n8.x4.shared.b16 {%0,%1,%2,%3}, [%4];"
        : "=r"(r[0]), "=r"(r[1]), "=r"(r[2]), "=r"(r[3]) : "r"(a));
}
__device__ __forceinline__ void ldsm_x4_t(unsigned* r, const void* p) {
    unsigned a = smem_u32(p);
    asm volatile("ldmatrix.sync.aligned.m8n8.x4.trans.shared.b16 {%0,%1,%2,%3}, [%4];"
        : "=r"(r[0]), "=r"(r[1]), "=r"(r[2]), "=r"(r[3]) : "r"(a));
}
__device__ __forceinline__ void mma_bf16(float* d, const unsigned* a, const unsigned* b) {
    asm volatile(
        "mma.sync.aligned.m16n8k16.row.col.f32.bf16.bf16.f32 "
        "{%0,%1,%2,%3}, {%4,%5,%6,%7}, {%8,%9}, {%0,%1,%2,%3};"
        : "+f"(d[0]), "+f"(d[1]), "+f"(d[2]), "+f"(d[3])
        : "r"(a[0]), "r"(a[1]), "r"(a[2]), "r"(a[3]), "r"(b[0]), "r"(b[1]));
}

__global__ void __launch_bounds__(256, 2)
gemm_bf16x3(const __nv_bfloat16* __restrict__ Ah, const __nv_bfloat16* __restrict__ Al,
            const __nv_bfloat16* __restrict__ Bh, const __nv_bfloat16* __restrict__ Bl,
            const float* __restrict__ bias, float* __restrict__ C,
            int M, int N, int K)
{
    extern __shared__ __nv_bfloat16 smem[];

    const int bm = blockIdx.y * 128;
    const int bn = blockIdx.x * 128;
    const int tid  = threadIdx.x;
    const int warp = tid >> 5;
    const int lane = tid & 31;
    const int wm = (warp >> 2) * 64;
    const int wn = (warp & 3)  * 32;

    const int ar0 = tid >> 2;           // A row base (0..63), +64
    const int ac  = (tid & 3) * 8;
    const int br0 = tid >> 4;           // B row base (0..15), +16
    const int bc  = (tid & 15) * 8;

    float acc[4][4][4] = {};

    auto issue = [&](int kt, int stage) {
        __nv_bfloat16* dAh = smem + stage * STAGE_ELEMS;
        __nv_bfloat16* dAl = dAh + SA_ELEMS;
        #pragma unroll
        for (int rr = 0; rr < 2; rr++) {
            const int r = ar0 + rr * 64;
            const size_t g = (size_t)(bm + r) * K + kt + ac;
            cp16(smem_u32(&dAh[r * AST + ac]), Ah + g);
            cp16(smem_u32(&dAl[r * AST + ac]), Al + g);
        }
        __nv_bfloat16* dBh = dAl + SA_ELEMS;
        __nv_bfloat16* dBl = dBh + SB_ELEMS;
        #pragma unroll
        for (int rr = 0; rr < 2; rr++) {
            const int r = br0 + rr * 16;
            const size_t g = (size_t)(kt + r) * N + bn + bc;
            cp16(smem_u32(&dBh[r * BST + bc]), Bh + g);
            cp16(smem_u32(&dBl[r * BST + bc]), Bl + g);
        }
    };

    const int nk = K / 32;   // 12
    issue(0, 0); cp_commit();
    issue(32, 1); cp_commit();

    #pragma unroll 1
    for (int it = 0; it < nk; it++) {
        const int cur = it % NSTAGE;

        if (it + 2 < nk) cp_wait1(); else cp_wait0();
        // Single barrier per slab: also certifies all warps finished reading
        // stage (it-1)%NSTAGE, which is exactly what issue(it+2) overwrites.
        __syncthreads();
        if (it + 2 < nk) {
            issue((it + 2) * 32, (it + 2) % NSTAGE);
            cp_commit();
        }

        const __nv_bfloat16* pAh = smem + cur * STAGE_ELEMS;
        const __nv_bfloat16* pAl = pAh + SA_ELEMS;
        const __nv_bfloat16* pBh = pAl + SA_ELEMS;
        const __nv_bfloat16* pBl = pBh + SB_ELEMS;

        #pragma unroll
        for (int ks = 0; ks < 32; ks += 16) {
            unsigned af[4][4];               // A-hi, later overwritten with A-lo
            unsigned bh[2][4], bl[2][4];
            const int ar  = lane & 15;
            const int akc = ks + ((lane >> 4) << 3);
            const int bkr = ks + (lane & 15);
            const int bcc = ((lane >> 4) << 3);

            #pragma unroll
            for (int mi = 0; mi < 4; mi++)
                ldsm_x4(af[mi], &pAh[(wm + mi * 16 + ar) * AST + akc]);
            #pragma unroll
            for (int nb = 0; nb < 2; nb++) {
                ldsm_x4_t(bh[nb], &pBh[bkr * BST + wn + nb * 16 + bcc]);
                ldsm_x4_t(bl[nb], &pBl[bkr * BST + wn + nb * 16 + bcc]);
            }
            #pragma unroll
            for (int mi = 0; mi < 4; mi++)
                #pragma unroll
                for (int ni = 0; ni < 4; ni++) {
                    mma_bf16(acc[mi][ni], af[mi], &bh[ni >> 1][(ni & 1) * 2]);
                    mma_bf16(acc[mi][ni], af[mi], &bl[ni >> 1][(ni & 1) * 2]);
                }
            #pragma unroll
            for (int mi = 0; mi < 4; mi++)
                ldsm_x4(af[mi], &pAl[(wm + mi * 16 + ar) * AST + akc]);
            #pragma unroll
            for (int mi = 0; mi < 4; mi++)
                #pragma unroll
                for (int ni = 0; ni < 4; ni++)
                    mma_bf16(acc[mi][ni], af[mi], &bh[ni >> 1][(ni & 1) * 2]);
        }
        // no bottom barrier (see comment above)
    }

    // Epilogue
    #pragma unroll
    for (int ni = 0; ni < 4; ni++) {
        const int col = bn + wn + ni * 8 + (lane & 3) * 2;
        const float bx = bias[col];
        const float by = bias[col + 1];
        #pragma unroll
        for (int mi = 0; mi < 4; mi++) {
            const int row = bm + wm + mi * 16 + (lane >> 2);
            float* a4 = acc[mi][ni];
            *(float2*)&C[(size_t)row * N + col] =
                make_float2(a4[0] + bx, a4[1] + by);
            *(float2*)&C[(size_t)(row + 8) * N + col] =
                make_float2(a4[2] + bx, a4[3] + by);
        }
    }
}

// ---------------------------------------------------------------------------
// Window attention: one block per (window, head), fused scores+softmax pass.
// ---------------------------------------------------------------------------
__global__ void __launch_bounds__(256)
win_attn(const float* __restrict__ qkv, const float* __restrict__ biasx,
         __nv_bfloat16* __restrict__ outh, __nv_bfloat16* __restrict__ outl)
{
    const int b = blockIdx.x;
    const int h = blockIdx.y;
    const int tid = threadIdx.x;

    __shared__ float qs[NTOK][HD + 1];
    __shared__ float ks[NTOK][HD + 1];
    __shared__ float vs[NTOK][HD + 1];
    __shared__ float at[NTOK][NTOK + 1];

    const float scale = 0.17677669529663687f;

    for (int idx = tid; idx < NTOK * HD; idx += 256) {
        const int n = idx >> 5, d = idx & 31;
        const size_t base = ((size_t)b * NTOK + n) * QKV_N + h * HD + d;
        qs[n][d] = qkv[base] * scale;
        ks[n][d] = qkv[base + DIMC];
        vs[n][d] = qkv[base + 2 * DIMC];
    }
    __syncthreads();

    // Fused scores + bias + softmax: one warp per row n
    const int warp = tid >> 5, lane = tid & 31;
    const float* brow_base = biasx + (size_t)h * NTOK * NTOK;
    for (int n = warp; n < NTOK; n += 8) {
        const int m2 = lane + 32;
        float v1 = 0.f, v2 = 0.f;
        #pragma unroll
        for (int d = 0; d < HD; d++) {
            const float q = qs[n][d];
            v1 = fmaf(q, ks[lane][d], v1);
            if (m2 < NTOK) v2 = fmaf(q, ks[m2][d], v2);
        }
        const float* brow = brow_base + n * NTOK;
        v1 += brow[lane];
        v2 = (m2 < NTOK) ? v2 + brow[m2] : -CUDART_INF_F;
        float mx = fmaxf(v1, v2);
        #pragma unroll
        for (int o = 16; o; o >>= 1) mx = fmaxf(mx, __shfl_xor_sync(0xFFFFFFFFu, mx, o));
        float e1 = __expf(v1 - mx);
        float e2 = (m2 < NTOK) ? __expf(v2 - mx) : 0.f;
        float sm = e1 + e2;
        #pragma unroll
        for (int o = 16; o; o >>= 1) sm += __shfl_xor_sync(0xFFFFFFFFu, sm, o);
        const float inv = __frcp_rn(sm);
        at[n][lane] = e1 * inv;
        if (m2 < NTOK) at[n][m2] = e2 * inv;
    }
    __syncthreads();

    for (int idx = tid; idx < NTOK * HD; idx += 256) {
        const int n = idx >> 5, d = idx & 31;
        float s = 0.f;
        #pragma unroll
        for (int m = 0; m < NTOK; m++) s = fmaf(at[n][m], vs[m][d], s);
        const size_t o = ((size_t)b * NTOK + n) * DIMC + h * HD + d;
        __nv_bfloat16 hv, lv;
        split1(s, hv, lv);
        outh[o] = hv;
        outl[o] = lv;
    }
}

// ---------------------------------------------------------------------------
extern "C" void kernel_launch(void* const* d_in, const int* in_sizes, int n_in,
                              void* d_out, int out_size)
{
    const float* x          = (const float*)d_in[0];
    const float* qkv_w      = (const float*)d_in[1];
    const float* qkv_b      = (const float*)d_in[2];
    const float* proj_w     = (const float*)d_in[3];
    const float* proj_b     = (const float*)d_in[4];
    const float* bias_table = (const float*)d_in[5];
    const int*   rpi        = (const int*)d_in[6];
    float* out = (float*)d_out;

    float *qkv, *biasx;
    __nv_bfloat16 *xh, *xl, *ah, *al, *qwh, *qwl, *pwh, *pwl;
    cudaGetSymbolAddress((void**)&qkv, g_qkv);
    cudaGetSymbolAddress((void**)&xh, g_xh);
    cudaGetSymbolAddress((void**)&xl, g_xl);
    cudaGetSymbolAddress((void**)&ah, g_ah);
    cudaGetSymbolAddress((void**)&al, g_al);
    cudaGetSymbolAddress((void**)&qwh, g_qwh);
    cudaGetSymbolAddress((void**)&qwl, g_qwl);
    cudaGetSymbolAddress((void**)&pwh, g_pwh);
    cudaGetSymbolAddress((void**)&pwl, g_pwl);
    cudaGetSymbolAddress((void**)&biasx, g_bias);

    cudaFuncSetAttribute(gemm_bf16x3,
                         cudaFuncAttributeMaxDynamicSharedMemorySize, GEMM_SMEM);

    // 0) splits + bias expansion
    {
        size_t n4 = (size_t)MROWS * DIMC / 4;
        split_f32<<<(unsigned)((n4 + 255) / 256), 256>>>(x, xh, xl, n4);
        size_t w4 = (size_t)KDIM * QKV_N / 4;
        split_f32<<<(unsigned)((w4 + 255) / 256), 256>>>(qkv_w, qwh, qwl, w4);
        size_t p4 = (size_t)KDIM * DIMC / 4;
        split_f32<<<(unsigned)((p4 + 255) / 256), 256>>>(proj_w, pwh, pwl, p4);
        expand_bias<<<(NHEADS * NTOK * NTOK + 255) / 256, 256>>>(bias_table, rpi, biasx);
    }
    // 1) QKV GEMM
    {
        dim3 grid(QKV_N / 128, MROWS / 128);
        gemm_bf16x3<<<grid, 256, GEMM_SMEM>>>(xh, xl, qwh, qwl, qkv_b, qkv,
                                              MROWS, QKV_N, KDIM);
    }
    // 2) Window attention
    {
        dim3 grid(NWIN, NHEADS);
        win_attn<<<grid, 256>>>(qkv, biasx, ah, al);
    }
    // 3) Proj GEMM
    {
        dim3 grid(DIMC / 128, MROWS / 128);
        gemm_bf16x3<<<grid, 256, GEMM_SMEM>>>(ah, al, pwh, pwl, proj_b, out,
                                              MROWS, DIMC, KDIM);
    }
}

// round 9
// speedup vs baseline: 1.3918x; 1.0221x over previous
#include <cuda_runtime.h>
#include <cuda_bf16.h>
#include <math_constants.h>
#include <cstdint>

#define DIMC     384
#define NHEADS   12
#define HD       32
#define NTOK     49
#define NWIN     4096
#define MROWS    (NWIN * NTOK)   // 200704
#define QKV_N    (3 * DIMC)      // 1152
#define KDIM     384

// Scratch (device globals — no allocation allowed)
__device__ float         g_qkv[(size_t)MROWS * QKV_N];
__device__ __nv_bfloat16 g_xh [(size_t)MROWS * DIMC];
__device__ __nv_bfloat16 g_xl [(size_t)MROWS * DIMC];
__device__ __nv_bfloat16 g_ah [(size_t)MROWS * DIMC];
__device__ __nv_bfloat16 g_al [(size_t)MROWS * DIMC];
__device__ __nv_bfloat16 g_qwh[(size_t)KDIM * QKV_N];
__device__ __nv_bfloat16 g_qwl[(size_t)KDIM * QKV_N];
__device__ __nv_bfloat16 g_pwh[(size_t)KDIM * DIMC];
__device__ __nv_bfloat16 g_pwl[(size_t)KDIM * DIMC];
__device__ float         g_bias[NHEADS * NTOK * NTOK];   // expanded bias

// ---------------------------------------------------------------------------
__device__ __forceinline__ void split1(float x, __nv_bfloat16& h, __nv_bfloat16& l) {
    h = __float2bfloat16(x);
    l = __float2bfloat16(x - __bfloat162float(h));
}
__device__ __forceinline__ void split2(float x0, float x1,
                                       __nv_bfloat162& h, __nv_bfloat162& l) {
    __nv_bfloat16 h0, l0, h1, l1;
    split1(x0, h0, l0);
    split1(x1, h1, l1);
    h = __nv_bfloat162(h0, h1);
    l = __nv_bfloat162(l0, l1);
}

__global__ void __launch_bounds__(256)
split_f32(const float* __restrict__ in, __nv_bfloat16* __restrict__ hi,
          __nv_bfloat16* __restrict__ lo, size_t n4)
{
    size_t i = (size_t)blockIdx.x * blockDim.x + threadIdx.x;
    if (i >= n4) return;
    float4 v = ((const float4*)in)[i];
    __nv_bfloat162 h0, l0, h1, l1;
    split2(v.x, v.y, h0, l0);
    split2(v.z, v.w, h1, l1);
    ((__nv_bfloat162*)hi)[i * 2]     = h0;
    ((__nv_bfloat162*)hi)[i * 2 + 1] = h1;
    ((__nv_bfloat162*)lo)[i * 2]     = l0;
    ((__nv_bfloat162*)lo)[i * 2 + 1] = l1;
}

// Expand bias_table[rpi[nm]*12+h] -> g_bias[h][n][m]
__global__ void __launch_bounds__(256)
expand_bias(const float* __restrict__ bias_table, const int* __restrict__ rpi,
            float* __restrict__ out)
{
    int i = blockIdx.x * blockDim.x + threadIdx.x;
    if (i >= NHEADS * NTOK * NTOK) return;
    const int h = i / (NTOK * NTOK);
    const int nm = i - h * (NTOK * NTOK);
    out[i] = bias_table[rpi[nm] * NHEADS + h];
}

// ---------------------------------------------------------------------------
// Tensor-core GEMM, bf16x3 (hh+hl+lh), 3-stage cp.async, ONE sync per slab,
// compile-time K=384 (fully unrolled).  Ordering per slab: WAIT -> SYNC ->
// ISSUE -> COMPUTE (wait must precede the barrier: cp.async completion is
// per-thread; the barrier is what publishes the data to all threads).
// BM=128, BN=128, BK=32, 256 threads (2x4 warps), warp tile 64x32, 2 CTAs/SM.
// ---------------------------------------------------------------------------
#define AST 40
#define BST 136
#define SA_ELEMS (128 * AST)
#define SB_ELEMS (32 * BST)
#define STAGE_ELEMS (2 * SA_ELEMS + 2 * SB_ELEMS)
#define NSTAGE 3
#define GEMM_SMEM (NSTAGE * STAGE_ELEMS * 2)
#define NK (KDIM / 32)   // 12

__device__ __forceinline__ uint32_t smem_u32(const void* p) {
    return (uint32_t)__cvta_generic_to_shared(p);
}
__device__ __forceinline__ void cp16(uint32_t dst, const void* src) {
    asm volatile("cp.async.cg.shared.global [%0], [%1], 16;" :: "r"(dst), "l"(src));
}
__device__ __forceinline__ void cp_commit() { asm volatile("cp.async.commit_group;"); }
__device__ __forceinline__ void cp_wait0()  { asm volatile("cp.async.wait_group 0;"); }
__device__ __forceinline__ void cp_wait1()  { asm volatile("cp.async.wait_group 1;"); }

__device__ __forceinline__ void ldsm_x4(unsigned* r, const void* p) {
    unsigned a = smem_u32(p);
    asm volatile("ldmatrix.sync.aligned.m8n8.x4.shared.b16 {%0,%1,%2,%3}, [%4];"
        : "=r"(r[0]), "=r"(r[1]), "=r"(r[2]), "=r"(r[3]) : "r"(a));
}
__device__ __forceinline__ void ldsm_x4_t(unsigned* r, const void* p) {
    unsigned a = smem_u32(p);
    asm volatile("ldmatrix.sync.aligned.m8n8.x4.trans.shared.b16 {%0,%1,%2,%3}, [%4];"
        : "=r"(r[0]), "=r"(r[1]), "=r"(r[2]), "=r"(r[3]) : "r"(a));
}
__device__ __forceinline__ void mma_bf16(float* d, const unsigned* a, const unsigned* b) {
    asm volatile(
        "mma.sync.aligned.m16n8k16.row.col.f32.bf16.bf16.f32 "
        "{%0,%1,%2,%3}, {%4,%5,%6,%7}, {%8,%9}, {%0,%1,%2,%3};"
        : "+f"(d[0]), "+f"(d[1]), "+f"(d[2]), "+f"(d[3])
        : "r"(a[0]), "r"(a[1]), "r"(a[2]), "r"(a[3]), "r"(b[0]), "r"(b[1]));
}

__global__ void __launch_bounds__(256, 2)
gemm_bf16x3(const __nv_bfloat16* __restrict__ Ah, const __nv_bfloat16* __restrict__ Al,
            const __nv_bfloat16* __restrict__ Bh, const __nv_bfloat16* __restrict__ Bl,
            const float* __restrict__ bias, float* __restrict__ C,
            int M, int N)
{
    extern __shared__ __nv_bfloat16 smem[];

    const int bm = blockIdx.y * 128;
    const int bn = blockIdx.x * 128;
    const int tid  = threadIdx.x;
    const int warp = tid >> 5;
    const int lane = tid & 31;
    const int wm = (warp >> 2) * 64;
    const int wn = (warp & 3)  * 32;

    const int ar0 = tid >> 2;
    const int ac  = (tid & 3) * 8;
    const int br0 = tid >> 4;
    const int bc  = (tid & 15) * 8;

    float acc[4][4][4] = {};

    auto issue = [&](int kt, int stage) {
        __nv_bfloat16* dAh = smem + stage * STAGE_ELEMS;
        __nv_bfloat16* dAl = dAh + SA_ELEMS;
        #pragma unroll
        for (int rr = 0; rr < 2; rr++) {
            const int r = ar0 + rr * 64;
            const size_t g = (size_t)(bm + r) * KDIM + kt + ac;
            cp16(smem_u32(&dAh[r * AST + ac]), Ah + g);
            cp16(smem_u32(&dAl[r * AST + ac]), Al + g);
        }
        __nv_bfloat16* dBh = dAl + SA_ELEMS;
        __nv_bfloat16* dBl = dBh + SB_ELEMS;
        #pragma unroll
        for (int rr = 0; rr < 2; rr++) {
            const int r = br0 + rr * 16;
            const size_t g = (size_t)(kt + r) * N + bn + bc;
            cp16(smem_u32(&dBh[r * BST + bc]), Bh + g);
            cp16(smem_u32(&dBl[r * BST + bc]), Bl + g);
        }
    };

    issue(0, 0); cp_commit();
    issue(32, 1); cp_commit();

    #pragma unroll
    for (int it = 0; it < NK; it++) {
        const int cur = it % NSTAGE;

        // 1) per-thread completion of the current stage's copies
        if (it + 2 < NK) cp_wait1(); else cp_wait0();
        // 2) publish to all threads + certify stage (it-1)%3 free for overwrite
        __syncthreads();
        // 3) refill the freed stage
        if (it + 2 < NK) {
            issue((it + 2) * 32, (it + 2) % NSTAGE);
            cp_commit();
        }

        const __nv_bfloat16* pAh = smem + cur * STAGE_ELEMS;
        const __nv_bfloat16* pAl = pAh + SA_ELEMS;
        const __nv_bfloat16* pBh = pAl + SA_ELEMS;
        const __nv_bfloat16* pBl = pBh + SB_ELEMS;

        #pragma unroll
        for (int ks = 0; ks < 32; ks += 16) {
            unsigned af[4][4];               // A-hi, later overwritten with A-lo
            unsigned bh[2][4], bl[2][4];
            const int ar  = lane & 15;
            const int akc = ks + ((lane >> 4) << 3);
            const int bkr = ks + (lane & 15);
            const int bcc = ((lane >> 4) << 3);

            #pragma unroll
            for (int mi = 0; mi < 4; mi++)
                ldsm_x4(af[mi], &pAh[(wm + mi * 16 + ar) * AST + akc]);
            #pragma unroll
            for (int nb = 0; nb < 2; nb++) {
                ldsm_x4_t(bh[nb], &pBh[bkr * BST + wn + nb * 16 + bcc]);
                ldsm_x4_t(bl[nb], &pBl[bkr * BST + wn + nb * 16 + bcc]);
            }
            #pragma unroll
            for (int mi = 0; mi < 4; mi++)
                #pragma unroll
                for (int ni = 0; ni < 4; ni++) {
                    mma_bf16(acc[mi][ni], af[mi], &bh[ni >> 1][(ni & 1) * 2]);
                    mma_bf16(acc[mi][ni], af[mi], &bl[ni >> 1][(ni & 1) * 2]);
                }
            #pragma unroll
            for (int mi = 0; mi < 4; mi++)
                ldsm_x4(af[mi], &pAl[(wm + mi * 16 + ar) * AST + akc]);
            #pragma unroll
            for (int mi = 0; mi < 4; mi++)
                #pragma unroll
                for (int ni = 0; ni < 4; ni++)
                    mma_bf16(acc[mi][ni], af[mi], &bh[ni >> 1][(ni & 1) * 2]);
        }
        // no bottom barrier: the top barrier of the next slab certifies reads
    }

    // Epilogue
    #pragma unroll
    for (int ni = 0; ni < 4; ni++) {
        const int col = bn + wn + ni * 8 + (lane & 3) * 2;
        const float bx = bias[col];
        const float by = bias[col + 1];
        #pragma unroll
        for (int mi = 0; mi < 4; mi++) {
            const int row = bm + wm + mi * 16 + (lane >> 2);
            float* a4 = acc[mi][ni];
            *(float2*)&C[(size_t)row * N + col] =
                make_float2(a4[0] + bx, a4[1] + by);
            *(float2*)&C[(size_t)(row + 8) * N + col] =
                make_float2(a4[2] + bx, a4[3] + by);
        }
    }
}

// ---------------------------------------------------------------------------
// Window attention: one block per (window, head), fused scores+softmax pass.
// ---------------------------------------------------------------------------
__global__ void __launch_bounds__(256)
win_attn(const float* __restrict__ qkv, const float* __restrict__ biasx,
         __nv_bfloat16* __restrict__ outh, __nv_bfloat16* __restrict__ outl)
{
    const int b = blockIdx.x;
    const int h = blockIdx.y;
    const int tid = threadIdx.x;

    __shared__ float qs[NTOK][HD + 1];
    __shared__ float ks[NTOK][HD + 1];
    __shared__ float vs[NTOK][HD + 1];
    __shared__ float at[NTOK][NTOK + 1];

    const float scale = 0.17677669529663687f;

    for (int idx = tid; idx < NTOK * HD; idx += 256) {
        const int n = idx >> 5, d = idx & 31;
        const size_t base = ((size_t)b * NTOK + n) * QKV_N + h * HD + d;
        qs[n][d] = qkv[base] * scale;
        ks[n][d] = qkv[base + DIMC];
        vs[n][d] = qkv[base + 2 * DIMC];
    }
    __syncthreads();

    const int warp = tid >> 5, lane = tid & 31;
    const float* brow_base = biasx + (size_t)h * NTOK * NTOK;
    for (int n = warp; n < NTOK; n += 8) {
        const int m2 = lane + 32;
        float v1 = 0.f, v2 = 0.f;
        #pragma unroll
        for (int d = 0; d < HD; d++) {
            const float q = qs[n][d];
            v1 = fmaf(q, ks[lane][d], v1);
            if (m2 < NTOK) v2 = fmaf(q, ks[m2][d], v2);
        }
        const float* brow = brow_base + n * NTOK;
        v1 += brow[lane];
        v2 = (m2 < NTOK) ? v2 + brow[m2] : -CUDART_INF_F;
        float mx = fmaxf(v1, v2);
        #pragma unroll
        for (int o = 16; o; o >>= 1) mx = fmaxf(mx, __shfl_xor_sync(0xFFFFFFFFu, mx, o));
        float e1 = __expf(v1 - mx);
        float e2 = (m2 < NTOK) ? __expf(v2 - mx) : 0.f;
        float sm = e1 + e2;
        #pragma unroll
        for (int o = 16; o; o >>= 1) sm += __shfl_xor_sync(0xFFFFFFFFu, sm, o);
        const float inv = __frcp_rn(sm);
        at[n][lane] = e1 * inv;
        if (m2 < NTOK) at[n][m2] = e2 * inv;
    }
    __syncthreads();

    for (int idx = tid; idx < NTOK * HD; idx += 256) {
        const int n = idx >> 5, d = idx & 31;
        float s = 0.f;
        #pragma unroll
        for (int m = 0; m < NTOK; m++) s = fmaf(at[n][m], vs[m][d], s);
        const size_t o = ((size_t)b * NTOK + n) * DIMC + h * HD + d;
        __nv_bfloat16 hv, lv;
        split1(s, hv, lv);
        outh[o] = hv;
        outl[o] = lv;
    }
}

// ---------------------------------------------------------------------------
extern "C" void kernel_launch(void* const* d_in, const int* in_sizes, int n_in,
                              void* d_out, int out_size)
{
    const float* x          = (const float*)d_in[0];
    const float* qkv_w      = (const float*)d_in[1];
    const float* qkv_b      = (const float*)d_in[2];
    const float* proj_w     = (const float*)d_in[3];
    const float* proj_b     = (const float*)d_in[4];
    const float* bias_table = (const float*)d_in[5];
    const int*   rpi        = (const int*)d_in[6];
    float* out = (float*)d_out;

    float *qkv, *biasx;
    __nv_bfloat16 *xh, *xl, *ah, *al, *qwh, *qwl, *pwh, *pwl;
    cudaGetSymbolAddress((void**)&qkv, g_qkv);
    cudaGetSymbolAddress((void**)&xh, g_xh);
    cudaGetSymbolAddress((void**)&xl, g_xl);
    cudaGetSymbolAddress((void**)&ah, g_ah);
    cudaGetSymbolAddress((void**)&al, g_al);
    cudaGetSymbolAddress((void**)&qwh, g_qwh);
    cudaGetSymbolAddress((void**)&qwl, g_qwl);
    cudaGetSymbolAddress((void**)&pwh, g_pwh);
    cudaGetSymbolAddress((void**)&pwl, g_pwl);
    cudaGetSymbolAddress((void**)&biasx, g_bias);

    cudaFuncSetAttribute(gemm_bf16x3,
                         cudaFuncAttributeMaxDynamicSharedMemorySize, GEMM_SMEM);

    // 0) splits + bias expansion
    {
        size_t n4 = (size_t)MROWS * DIMC / 4;
        split_f32<<<(unsigned)((n4 + 255) / 256), 256>>>(x, xh, xl, n4);
        size_t w4 = (size_t)KDIM * QKV_N / 4;
        split_f32<<<(unsigned)((w4 + 255) / 256), 256>>>(qkv_w, qwh, qwl, w4);
        size_t p4 = (size_t)KDIM * DIMC / 4;
        split_f32<<<(unsigned)((p4 + 255) / 256), 256>>>(proj_w, pwh, pwl, p4);
        expand_bias<<<(NHEADS * NTOK * NTOK + 255) / 256, 256>>>(bias_table, rpi, biasx);
    }
    // 1) QKV GEMM
    {
        dim3 grid(QKV_N / 128, MROWS / 128);
        gemm_bf16x3<<<grid, 256, GEMM_SMEM>>>(xh, xl, qwh, qwl, qkv_b, qkv,
                                              MROWS, QKV_N);
    }
    // 2) Window attention
    {
        dim3 grid(NWIN, NHEADS);
        win_attn<<<grid, 256>>>(qkv, biasx, ah, al);
    }
    // 3) Proj GEMM
    {
        dim3 grid(DIMC / 128, MROWS / 128);
        gemm_bf16x3<<<grid, 256, GEMM_SMEM>>>(ah, al, pwh, pwl, proj_b, out,
                                              MROWS, DIMC);
    }
}

// round 10
// speedup vs baseline: 1.8302x; 1.3150x over previous
#include <cuda_runtime.h>
#include <cuda_bf16.h>
#include <cuda_fp16.h>
#include <math_constants.h>
#include <cstdint>

#define DIMC     384
#define NHEADS   12
#define HD       32
#define NTOK     49
#define NWIN     4096
#define MROWS    (NWIN * NTOK)   // 200704
#define QKV_N    (3 * DIMC)      // 1152
#define KDIM     384

// Scratch (device globals — no allocation allowed)
__device__ float         g_qkv[(size_t)MROWS * QKV_N];
__device__ __half        g_xf [(size_t)MROWS * DIMC];     // x in fp16
__device__ __half        g_qwf[(size_t)KDIM * QKV_N];     // qkv_w in fp16
__device__ __nv_bfloat16 g_ah [(size_t)MROWS * DIMC];     // attn out hi (bf16)
__device__ __nv_bfloat16 g_al [(size_t)MROWS * DIMC];     // attn out lo (bf16)
__device__ __nv_bfloat16 g_pwh[(size_t)KDIM * DIMC];
__device__ __nv_bfloat16 g_pwl[(size_t)KDIM * DIMC];
__device__ float         g_bias[NHEADS * NTOK * NTOK];    // expanded bias

// ---------------------------------------------------------------------------
__device__ __forceinline__ void split1(float x, __nv_bfloat16& h, __nv_bfloat16& l) {
    h = __float2bfloat16(x);
    l = __float2bfloat16(x - __bfloat162float(h));
}

// fp32 -> fp16 conversion (4 elems/thread)
__global__ void __launch_bounds__(256)
conv_f16(const float* __restrict__ in, __half* __restrict__ out, size_t n4)
{
    size_t i = (size_t)blockIdx.x * blockDim.x + threadIdx.x;
    if (i >= n4) return;
    float4 v = ((const float4*)in)[i];
    __half2* o = (__half2*)out;
    o[i * 2]     = __floats2half2_rn(v.x, v.y);
    o[i * 2 + 1] = __floats2half2_rn(v.z, v.w);
}

// fp32 -> (hi, lo) bf16 split (4 elems/thread)
__global__ void __launch_bounds__(256)
split_f32(const float* __restrict__ in, __nv_bfloat16* __restrict__ hi,
          __nv_bfloat16* __restrict__ lo, size_t n4)
{
    size_t i = (size_t)blockIdx.x * blockDim.x + threadIdx.x;
    if (i >= n4) return;
    float4 v = ((const float4*)in)[i];
    __nv_bfloat16 h0, l0, h1, l1, h2, l2, h3, l3;
    split1(v.x, h0, l0); split1(v.y, h1, l1);
    split1(v.z, h2, l2); split1(v.w, h3, l3);
    ((__nv_bfloat162*)hi)[i * 2]     = __nv_bfloat162(h0, h1);
    ((__nv_bfloat162*)hi)[i * 2 + 1] = __nv_bfloat162(h2, h3);
    ((__nv_bfloat162*)lo)[i * 2]     = __nv_bfloat162(l0, l1);
    ((__nv_bfloat162*)lo)[i * 2 + 1] = __nv_bfloat162(l2, l3);
}

// Expand bias_table[rpi[nm]*12+h] -> g_bias[h][n][m]
__global__ void __launch_bounds__(256)
expand_bias(const float* __restrict__ bias_table, const int* __restrict__ rpi,
            float* __restrict__ out)
{
    int i = blockIdx.x * blockDim.x + threadIdx.x;
    if (i >= NHEADS * NTOK * NTOK) return;
    const int h = i / (NTOK * NTOK);
    const int nm = i - h * (NTOK * NTOK);
    out[i] = bias_table[rpi[nm] * NHEADS + h];
}

// ---------------------------------------------------------------------------
// Shared GEMM plumbing
// ---------------------------------------------------------------------------
#define AST 40
#define BST 136
#define SA_ELEMS (128 * AST)
#define SB_ELEMS (32 * BST)
#define NSTAGE 3
#define NK (KDIM / 32)   // 12

__device__ __forceinline__ uint32_t smem_u32(const void* p) {
    return (uint32_t)__cvta_generic_to_shared(p);
}
__device__ __forceinline__ void cp16(uint32_t dst, const void* src) {
    asm volatile("cp.async.cg.shared.global [%0], [%1], 16;" :: "r"(dst), "l"(src));
}
__device__ __forceinline__ void cp_commit() { asm volatile("cp.async.commit_group;"); }
__device__ __forceinline__ void cp_wait0()  { asm volatile("cp.async.wait_group 0;"); }
__device__ __forceinline__ void cp_wait1()  { asm volatile("cp.async.wait_group 1;"); }

__device__ __forceinline__ void ldsm_x4(unsigned* r, const void* p) {
    unsigned a = smem_u32(p);
    asm volatile("ldmatrix.sync.aligned.m8n8.x4.shared.b16 {%0,%1,%2,%3}, [%4];"
        : "=r"(r[0]), "=r"(r[1]), "=r"(r[2]), "=r"(r[3]) : "r"(a));
}
__device__ __forceinline__ void ldsm_x4_t(unsigned* r, const void* p) {
    unsigned a = smem_u32(p);
    asm volatile("ldmatrix.sync.aligned.m8n8.x4.trans.shared.b16 {%0,%1,%2,%3}, [%4];"
        : "=r"(r[0]), "=r"(r[1]), "=r"(r[2]), "=r"(r[3]) : "r"(a));
}
__device__ __forceinline__ void mma_bf16(float* d, const unsigned* a, const unsigned* b) {
    asm volatile(
        "mma.sync.aligned.m16n8k16.row.col.f32.bf16.bf16.f32 "
        "{%0,%1,%2,%3}, {%4,%5,%6,%7}, {%8,%9}, {%0,%1,%2,%3};"
        : "+f"(d[0]), "+f"(d[1]), "+f"(d[2]), "+f"(d[3])
        : "r"(a[0]), "r"(a[1]), "r"(a[2]), "r"(a[3]), "r"(b[0]), "r"(b[1]));
}
__device__ __forceinline__ void mma_f16(float* d, const unsigned* a, const unsigned* b) {
    asm volatile(
        "mma.sync.aligned.m16n8k16.row.col.f32.f16.f16.f32 "
        "{%0,%1,%2,%3}, {%4,%5,%6,%7}, {%8,%9}, {%0,%1,%2,%3};"
        : "+f"(d[0]), "+f"(d[1]), "+f"(d[2]), "+f"(d[3])
        : "r"(a[0]), "r"(a[1]), "r"(a[2]), "r"(a[3]), "r"(b[0]), "r"(b[1]));
}

// ---------------------------------------------------------------------------
// FP16 single-term GEMM (QKV): C = A@B + bias.  Same schedule as bf16x3:
// 3-stage cp.async, WAIT -> SYNC -> ISSUE -> COMPUTE, one barrier per slab.
// ---------------------------------------------------------------------------
#define STAGE_F16 (SA_ELEMS + SB_ELEMS)
#define GEMM_SMEM_F16 (NSTAGE * STAGE_F16 * 2)   // 56832 B

__global__ void __launch_bounds__(256, 2)
gemm_f16(const __half* __restrict__ A, const __half* __restrict__ B,
         const float* __restrict__ bias, float* __restrict__ C,
         int M, int N)
{
    extern __shared__ __half smemh[];

    const int bm = blockIdx.y * 128;
    const int bn = blockIdx.x * 128;
    const int tid  = threadIdx.x;
    const int warp = tid >> 5;
    const int lane = tid & 31;
    const int wm = (warp >> 2) * 64;
    const int wn = (warp & 3)  * 32;

    const int ar0 = tid >> 2;
    const int ac  = (tid & 3) * 8;
    const int br0 = tid >> 4;
    const int bc  = (tid & 15) * 8;

    float acc[4][4][4] = {};

    auto issue = [&](int kt, int stage) {
        __half* dA = smemh + stage * STAGE_F16;
        #pragma unroll
        for (int rr = 0; rr < 2; rr++) {
            const int r = ar0 + rr * 64;
            cp16(smem_u32(&dA[r * AST + ac]), A + (size_t)(bm + r) * KDIM + kt + ac);
        }
        __half* dB = dA + SA_ELEMS;
        #pragma unroll
        for (int rr = 0; rr < 2; rr++) {
            const int r = br0 + rr * 16;
            cp16(smem_u32(&dB[r * BST + bc]), B + (size_t)(kt + r) * N + bn + bc);
        }
    };

    issue(0, 0); cp_commit();
    issue(32, 1); cp_commit();

    #pragma unroll
    for (int it = 0; it < NK; it++) {
        const int cur = it % NSTAGE;

        if (it + 2 < NK) cp_wait1(); else cp_wait0();
        __syncthreads();
        if (it + 2 < NK) {
            issue((it + 2) * 32, (it + 2) % NSTAGE);
            cp_commit();
        }

        const __half* pA = smemh + cur * STAGE_F16;
        const __half* pB = pA + SA_ELEMS;

        #pragma unroll
        for (int ks = 0; ks < 32; ks += 16) {
            unsigned af[4][4], bf[2][4];
            const int ar  = lane & 15;
            const int akc = ks + ((lane >> 4) << 3);
            const int bkr = ks + (lane & 15);
            const int bcc = ((lane >> 4) << 3);

            #pragma unroll
            for (int mi = 0; mi < 4; mi++)
                ldsm_x4(af[mi], &pA[(wm + mi * 16 + ar) * AST + akc]);
            #pragma unroll
            for (int nb = 0; nb < 2; nb++)
                ldsm_x4_t(bf[nb], &pB[bkr * BST + wn + nb * 16 + bcc]);

            #pragma unroll
            for (int mi = 0; mi < 4; mi++)
                #pragma unroll
                for (int ni = 0; ni < 4; ni++)
                    mma_f16(acc[mi][ni], af[mi], &bf[ni >> 1][(ni & 1) * 2]);
        }
    }

    #pragma unroll
    for (int ni = 0; ni < 4; ni++) {
        const int col = bn + wn + ni * 8 + (lane & 3) * 2;
        const float bx = bias[col];
        const float by = bias[col + 1];
        #pragma unroll
        for (int mi = 0; mi < 4; mi++) {
            const int row = bm + wm + mi * 16 + (lane >> 2);
            float* a4 = acc[mi][ni];
            *(float2*)&C[(size_t)row * N + col] =
                make_float2(a4[0] + bx, a4[1] + by);
            *(float2*)&C[(size_t)(row + 8) * N + col] =
                make_float2(a4[2] + bx, a4[3] + by);
        }
    }
}

// ---------------------------------------------------------------------------
// bf16x3 GEMM (proj) — unchanged from R8 winner.
// ---------------------------------------------------------------------------
#define STAGE_ELEMS (2 * SA_ELEMS + 2 * SB_ELEMS)
#define GEMM_SMEM (NSTAGE * STAGE_ELEMS * 2)

__global__ void __launch_bounds__(256, 2)
gemm_bf16x3(const __nv_bfloat16* __restrict__ Ah, const __nv_bfloat16* __restrict__ Al,
            const __nv_bfloat16* __restrict__ Bh, const __nv_bfloat16* __restrict__ Bl,
            const float* __restrict__ bias, float* __restrict__ C,
            int M, int N)
{
    extern __shared__ __nv_bfloat16 smem[];

    const int bm = blockIdx.y * 128;
    const int bn = blockIdx.x * 128;
    const int tid  = threadIdx.x;
    const int warp = tid >> 5;
    const int lane = tid & 31;
    const int wm = (warp >> 2) * 64;
    const int wn = (warp & 3)  * 32;

    const int ar0 = tid >> 2;
    const int ac  = (tid & 3) * 8;
    const int br0 = tid >> 4;
    const int bc  = (tid & 15) * 8;

    float acc[4][4][4] = {};

    auto issue = [&](int kt, int stage) {
        __nv_bfloat16* dAh = smem + stage * STAGE_ELEMS;
        __nv_bfloat16* dAl = dAh + SA_ELEMS;
        #pragma unroll
        for (int rr = 0; rr < 2; rr++) {
            const int r = ar0 + rr * 64;
            const size_t g = (size_t)(bm + r) * KDIM + kt + ac;
            cp16(smem_u32(&dAh[r * AST + ac]), Ah + g);
            cp16(smem_u32(&dAl[r * AST + ac]), Al + g);
        }
        __nv_bfloat16* dBh = dAl + SA_ELEMS;
        __nv_bfloat16* dBl = dBh + SB_ELEMS;
        #pragma unroll
        for (int rr = 0; rr < 2; rr++) {
            const int r = br0 + rr * 16;
            const size_t g = (size_t)(kt + r) * N + bn + bc;
            cp16(smem_u32(&dBh[r * BST + bc]), Bh + g);
            cp16(smem_u32(&dBl[r * BST + bc]), Bl + g);
        }
    };

    issue(0, 0); cp_commit();
    issue(32, 1); cp_commit();

    #pragma unroll
    for (int it = 0; it < NK; it++) {
        const int cur = it % NSTAGE;

        if (it + 2 < NK) cp_wait1(); else cp_wait0();
        __syncthreads();
        if (it + 2 < NK) {
            issue((it + 2) * 32, (it + 2) % NSTAGE);
            cp_commit();
        }

        const __nv_bfloat16* pAh = smem + cur * STAGE_ELEMS;
        const __nv_bfloat16* pAl = pAh + SA_ELEMS;
        const __nv_bfloat16* pBh = pAl + SA_ELEMS;
        const __nv_bfloat16* pBl = pBh + SB_ELEMS;

        #pragma unroll
        for (int ks = 0; ks < 32; ks += 16) {
            unsigned af[4][4];
            unsigned bh[2][4], bl[2][4];
            const int ar  = lane & 15;
            const int akc = ks + ((lane >> 4) << 3);
            const int bkr = ks + (lane & 15);
            const int bcc = ((lane >> 4) << 3);

            #pragma unroll
            for (int mi = 0; mi < 4; mi++)
                ldsm_x4(af[mi], &pAh[(wm + mi * 16 + ar) * AST + akc]);
            #pragma unroll
            for (int nb = 0; nb < 2; nb++) {
                ldsm_x4_t(bh[nb], &pBh[bkr * BST + wn + nb * 16 + bcc]);
                ldsm_x4_t(bl[nb], &pBl[bkr * BST + wn + nb * 16 + bcc]);
            }
            #pragma unroll
            for (int mi = 0; mi < 4; mi++)
                #pragma unroll
                for (int ni = 0; ni < 4; ni++) {
                    mma_bf16(acc[mi][ni], af[mi], &bh[ni >> 1][(ni & 1) * 2]);
                    mma_bf16(acc[mi][ni], af[mi], &bl[ni >> 1][(ni & 1) * 2]);
                }
            #pragma unroll
            for (int mi = 0; mi < 4; mi++)
                ldsm_x4(af[mi], &pAl[(wm + mi * 16 + ar) * AST + akc]);
            #pragma unroll
            for (int mi = 0; mi < 4; mi++)
                #pragma unroll
                for (int ni = 0; ni < 4; ni++)
                    mma_bf16(acc[mi][ni], af[mi], &bh[ni >> 1][(ni & 1) * 2]);
        }
    }

    #pragma unroll
    for (int ni = 0; ni < 4; ni++) {
        const int col = bn + wn + ni * 8 + (lane & 3) * 2;
        const float bx = bias[col];
        const float by = bias[col + 1];
        #pragma unroll
        for (int mi = 0; mi < 4; mi++) {
            const int row = bm + wm + mi * 16 + (lane >> 2);
            float* a4 = acc[mi][ni];
            *(float2*)&C[(size_t)row * N + col] =
                make_float2(a4[0] + bx, a4[1] + by);
            *(float2*)&C[(size_t)(row + 8) * N + col] =
                make_float2(a4[2] + bx, a4[3] + by);
        }
    }
}

// ---------------------------------------------------------------------------
// Window attention: one block per (window, head), fused scores+softmax pass.
// ---------------------------------------------------------------------------
__global__ void __launch_bounds__(256)
win_attn(const float* __restrict__ qkv, const float* __restrict__ biasx,
         __nv_bfloat16* __restrict__ outh, __nv_bfloat16* __restrict__ outl)
{
    const int b = blockIdx.x;
    const int h = blockIdx.y;
    const int tid = threadIdx.x;

    __shared__ float qs[NTOK][HD + 1];
    __shared__ float ks[NTOK][HD + 1];
    __shared__ float vs[NTOK][HD + 1];
    __shared__ float at[NTOK][NTOK + 1];

    const float scale = 0.17677669529663687f;

    for (int idx = tid; idx < NTOK * HD; idx += 256) {
        const int n = idx >> 5, d = idx & 31;
        const size_t base = ((size_t)b * NTOK + n) * QKV_N + h * HD + d;
        qs[n][d] = qkv[base] * scale;
        ks[n][d] = qkv[base + DIMC];
        vs[n][d] = qkv[base + 2 * DIMC];
    }
    __syncthreads();

    const int warp = tid >> 5, lane = tid & 31;
    const float* brow_base = biasx + (size_t)h * NTOK * NTOK;
    for (int n = warp; n < NTOK; n += 8) {
        const int m2 = lane + 32;
        float v1 = 0.f, v2 = 0.f;
        #pragma unroll
        for (int d = 0; d < HD; d++) {
            const float q = qs[n][d];
            v1 = fmaf(q, ks[lane][d], v1);
            if (m2 < NTOK) v2 = fmaf(q, ks[m2][d], v2);
        }
        const float* brow = brow_base + n * NTOK;
        v1 += brow[lane];
        v2 = (m2 < NTOK) ? v2 + brow[m2] : -CUDART_INF_F;
        float mx = fmaxf(v1, v2);
        #pragma unroll
        for (int o = 16; o; o >>= 1) mx = fmaxf(mx, __shfl_xor_sync(0xFFFFFFFFu, mx, o));
        float e1 = __expf(v1 - mx);
        float e2 = (m2 < NTOK) ? __expf(v2 - mx) : 0.f;
        float sm = e1 + e2;
        #pragma unroll
        for (int o = 16; o; o >>= 1) sm += __shfl_xor_sync(0xFFFFFFFFu, sm, o);
        const float inv = __frcp_rn(sm);
        at[n][lane] = e1 * inv;
        if (m2 < NTOK) at[n][m2] = e2 * inv;
    }
    __syncthreads();

    for (int idx = tid; idx < NTOK * HD; idx += 256) {
        const int n = idx >> 5, d = idx & 31;
        float s = 0.f;
        #pragma unroll
        for (int m = 0; m < NTOK; m++) s = fmaf(at[n][m], vs[m][d], s);
        const size_t o = ((size_t)b * NTOK + n) * DIMC + h * HD + d;
        __nv_bfloat16 hv, lv;
        split1(s, hv, lv);
        outh[o] = hv;
        outl[o] = lv;
    }
}

// ---------------------------------------------------------------------------
extern "C" void kernel_launch(void* const* d_in, const int* in_sizes, int n_in,
                              void* d_out, int out_size)
{
    const float* x          = (const float*)d_in[0];
    const float* qkv_w      = (const float*)d_in[1];
    const float* qkv_b      = (const float*)d_in[2];
    const float* proj_w     = (const float*)d_in[3];
    const float* proj_b     = (const float*)d_in[4];
    const float* bias_table = (const float*)d_in[5];
    const int*   rpi        = (const int*)d_in[6];
    float* out = (float*)d_out;

    float *qkv, *biasx;
    __half *xf, *qwf;
    __nv_bfloat16 *ah, *al, *pwh, *pwl;
    cudaGetSymbolAddress((void**)&qkv, g_qkv);
    cudaGetSymbolAddress((void**)&xf, g_xf);
    cudaGetSymbolAddress((void**)&qwf, g_qwf);
    cudaGetSymbolAddress((void**)&ah, g_ah);
    cudaGetSymbolAddress((void**)&al, g_al);
    cudaGetSymbolAddress((void**)&pwh, g_pwh);
    cudaGetSymbolAddress((void**)&pwl, g_pwl);
    cudaGetSymbolAddress((void**)&biasx, g_bias);

    cudaFuncSetAttribute(gemm_f16,
                         cudaFuncAttributeMaxDynamicSharedMemorySize, GEMM_SMEM_F16);
    cudaFuncSetAttribute(gemm_bf16x3,
                         cudaFuncAttributeMaxDynamicSharedMemorySize, GEMM_SMEM);

    // 0) conversions + bias expansion
    {
        size_t n4 = (size_t)MROWS * DIMC / 4;
        conv_f16<<<(unsigned)((n4 + 255) / 256), 256>>>(x, xf, n4);
        size_t w4 = (size_t)KDIM * QKV_N / 4;
        conv_f16<<<(unsigned)((w4 + 255) / 256), 256>>>(qkv_w, qwf, w4);
        size_t p4 = (size_t)KDIM * DIMC / 4;
        split_f32<<<(unsigned)((p4 + 255) / 256), 256>>>(proj_w, pwh, pwl, p4);
        expand_bias<<<(NHEADS * NTOK * NTOK + 255) / 256, 256>>>(bias_table, rpi, biasx);
    }
    // 1) QKV GEMM (fp16 single-term)
    {
        dim3 grid(QKV_N / 128, MROWS / 128);
        gemm_f16<<<grid, 256, GEMM_SMEM_F16>>>(xf, qwf, qkv_b, qkv, MROWS, QKV_N);
    }
    // 2) Window attention (fp32 in, bf16 hi/lo out)
    {
        dim3 grid(NWIN, NHEADS);
        win_attn<<<grid, 256>>>(qkv, biasx, ah, al);
    }
    // 3) Proj GEMM (bf16x3)
    {
        dim3 grid(DIMC / 128, MROWS / 128);
        gemm_bf16x3<<<grid, 256, GEMM_SMEM>>>(ah, al, pwh, pwl, proj_b, out,
                                              MROWS, DIMC);
    }
}

// round 11
// speedup vs baseline: 2.0668x; 1.1293x over previous
#include <cuda_runtime.h>
#include <cuda_bf16.h>
#include <cuda_fp16.h>
#include <math_constants.h>
#include <cstdint>

#define DIMC     384
#define NHEADS   12
#define HD       32
#define NTOK     49
#define NWIN     4096
#define MROWS    (NWIN * NTOK)   // 200704
#define QKV_N    (3 * DIMC)      // 1152
#define KDIM     384

// Scratch (device globals — no allocation allowed)
__device__ float  g_qkv[(size_t)MROWS * QKV_N];
__device__ __half g_xf [(size_t)MROWS * DIMC];     // x in fp16
__device__ __half g_qwf[(size_t)KDIM * QKV_N];     // qkv_w in fp16
__device__ __half g_af [(size_t)MROWS * DIMC];     // attn out in fp16
__device__ __half g_pwf[(size_t)KDIM * DIMC];      // proj_w in fp16
__device__ float  g_bias[NHEADS * NTOK * NTOK];    // expanded bias

// ---------------------------------------------------------------------------
// fp32 -> fp16 conversion (4 elems/thread)
__global__ void __launch_bounds__(256)
conv_f16(const float* __restrict__ in, __half* __restrict__ out, size_t n4)
{
    size_t i = (size_t)blockIdx.x * blockDim.x + threadIdx.x;
    if (i >= n4) return;
    float4 v = ((const float4*)in)[i];
    __half2* o = (__half2*)out;
    o[i * 2]     = __floats2half2_rn(v.x, v.y);
    o[i * 2 + 1] = __floats2half2_rn(v.z, v.w);
}

// Expand bias_table[rpi[nm]*12+h] -> g_bias[h][n][m]
__global__ void __launch_bounds__(256)
expand_bias(const float* __restrict__ bias_table, const int* __restrict__ rpi,
            float* __restrict__ out)
{
    int i = blockIdx.x * blockDim.x + threadIdx.x;
    if (i >= NHEADS * NTOK * NTOK) return;
    const int h = i / (NTOK * NTOK);
    const int nm = i - h * (NTOK * NTOK);
    out[i] = bias_table[rpi[nm] * NHEADS + h];
}

// ---------------------------------------------------------------------------
// FP16 tensor-core GEMM: C = A@B + bias.
// 3-stage cp.async, WAIT -> SYNC -> ISSUE -> COMPUTE, one barrier per slab.
// BM=128, BN=128, BK=32, 256 threads (2x4 warps), warp tile 64x32, 2 CTAs/SM,
// compile-time K=384 fully unrolled.
// ---------------------------------------------------------------------------
#define AST 40
#define BST 136
#define SA_ELEMS (128 * AST)
#define SB_ELEMS (32 * BST)
#define NSTAGE 3
#define NK (KDIM / 32)   // 12
#define STAGE_F16 (SA_ELEMS + SB_ELEMS)
#define GEMM_SMEM_F16 (NSTAGE * STAGE_F16 * 2)   // 56832 B

__device__ __forceinline__ uint32_t smem_u32(const void* p) {
    return (uint32_t)__cvta_generic_to_shared(p);
}
__device__ __forceinline__ void cp16(uint32_t dst, const void* src) {
    asm volatile("cp.async.cg.shared.global [%0], [%1], 16;" :: "r"(dst), "l"(src));
}
__device__ __forceinline__ void cp_commit() { asm volatile("cp.async.commit_group;"); }
__device__ __forceinline__ void cp_wait0()  { asm volatile("cp.async.wait_group 0;"); }
__device__ __forceinline__ void cp_wait1()  { asm volatile("cp.async.wait_group 1;"); }

__device__ __forceinline__ void ldsm_x4(unsigned* r, const void* p) {
    unsigned a = smem_u32(p);
    asm volatile("ldmatrix.sync.aligned.m8n8.x4.shared.b16 {%0,%1,%2,%3}, [%4];"
        : "=r"(r[0]), "=r"(r[1]), "=r"(r[2]), "=r"(r[3]) : "r"(a));
}
__device__ __forceinline__ void ldsm_x4_t(unsigned* r, const void* p) {
    unsigned a = smem_u32(p);
    asm volatile("ldmatrix.sync.aligned.m8n8.x4.trans.shared.b16 {%0,%1,%2,%3}, [%4];"
        : "=r"(r[0]), "=r"(r[1]), "=r"(r[2]), "=r"(r[3]) : "r"(a));
}
__device__ __forceinline__ void mma_f16(float* d, const unsigned* a, const unsigned* b) {
    asm volatile(
        "mma.sync.aligned.m16n8k16.row.col.f32.f16.f16.f32 "
        "{%0,%1,%2,%3}, {%4,%5,%6,%7}, {%8,%9}, {%0,%1,%2,%3};"
        : "+f"(d[0]), "+f"(d[1]), "+f"(d[2]), "+f"(d[3])
        : "r"(a[0]), "r"(a[1]), "r"(a[2]), "r"(a[3]), "r"(b[0]), "r"(b[1]));
}

__global__ void __launch_bounds__(256, 2)
gemm_f16(const __half* __restrict__ A, const __half* __restrict__ B,
         const float* __restrict__ bias, float* __restrict__ C,
         int M, int N)
{
    extern __shared__ __half smemh[];

    const int bm = blockIdx.y * 128;
    const int bn = blockIdx.x * 128;
    const int tid  = threadIdx.x;
    const int warp = tid >> 5;
    const int lane = tid & 31;
    const int wm = (warp >> 2) * 64;
    const int wn = (warp & 3)  * 32;

    const int ar0 = tid >> 2;
    const int ac  = (tid & 3) * 8;
    const int br0 = tid >> 4;
    const int bc  = (tid & 15) * 8;

    float acc[4][4][4] = {};

    auto issue = [&](int kt, int stage) {
        __half* dA = smemh + stage * STAGE_F16;
        #pragma unroll
        for (int rr = 0; rr < 2; rr++) {
            const int r = ar0 + rr * 64;
            cp16(smem_u32(&dA[r * AST + ac]), A + (size_t)(bm + r) * KDIM + kt + ac);
        }
        __half* dB = dA + SA_ELEMS;
        #pragma unroll
        for (int rr = 0; rr < 2; rr++) {
            const int r = br0 + rr * 16;
            cp16(smem_u32(&dB[r * BST + bc]), B + (size_t)(kt + r) * N + bn + bc);
        }
    };

    issue(0, 0); cp_commit();
    issue(32, 1); cp_commit();

    #pragma unroll
    for (int it = 0; it < NK; it++) {
        const int cur = it % NSTAGE;

        // per-thread completion of current stage, then publish + certify free
        if (it + 2 < NK) cp_wait1(); else cp_wait0();
        __syncthreads();
        if (it + 2 < NK) {
            issue((it + 2) * 32, (it + 2) % NSTAGE);
            cp_commit();
        }

        const __half* pA = smemh + cur * STAGE_F16;
        const __half* pB = pA + SA_ELEMS;

        #pragma unroll
        for (int ks = 0; ks < 32; ks += 16) {
            unsigned af[4][4], bf[2][4];
            const int ar  = lane & 15;
            const int akc = ks + ((lane >> 4) << 3);
            const int bkr = ks + (lane & 15);
            const int bcc = ((lane >> 4) << 3);

            #pragma unroll
            for (int mi = 0; mi < 4; mi++)
                ldsm_x4(af[mi], &pA[(wm + mi * 16 + ar) * AST + akc]);
            #pragma unroll
            for (int nb = 0; nb < 2; nb++)
                ldsm_x4_t(bf[nb], &pB[bkr * BST + wn + nb * 16 + bcc]);

            #pragma unroll
            for (int mi = 0; mi < 4; mi++)
                #pragma unroll
                for (int ni = 0; ni < 4; ni++)
                    mma_f16(acc[mi][ni], af[mi], &bf[ni >> 1][(ni & 1) * 2]);
        }
    }

    #pragma unroll
    for (int ni = 0; ni < 4; ni++) {
        const int col = bn + wn + ni * 8 + (lane & 3) * 2;
        const float bx = bias[col];
        const float by = bias[col + 1];
        #pragma unroll
        for (int mi = 0; mi < 4; mi++) {
            const int row = bm + wm + mi * 16 + (lane >> 2);
            float* a4 = acc[mi][ni];
            *(float2*)&C[(size_t)row * N + col] =
                make_float2(a4[0] + bx, a4[1] + by);
            *(float2*)&C[(size_t)(row + 8) * N + col] =
                make_float2(a4[2] + bx, a4[3] + by);
        }
    }
}

// ---------------------------------------------------------------------------
// Window attention: one block per (window, head), fused scores+softmax pass.
// Emits fp16 (feeds the fp16 proj GEMM).
// ---------------------------------------------------------------------------
__global__ void __launch_bounds__(256)
win_attn(const float* __restrict__ qkv, const float* __restrict__ biasx,
         __half* __restrict__ outf)
{
    const int b = blockIdx.x;
    const int h = blockIdx.y;
    const int tid = threadIdx.x;

    __shared__ float qs[NTOK][HD + 1];
    __shared__ float ks[NTOK][HD + 1];
    __shared__ float vs[NTOK][HD + 1];
    __shared__ float at[NTOK][NTOK + 1];

    const float scale = 0.17677669529663687f;

    for (int idx = tid; idx < NTOK * HD; idx += 256) {
        const int n = idx >> 5, d = idx & 31;
        const size_t base = ((size_t)b * NTOK + n) * QKV_N + h * HD + d;
        qs[n][d] = qkv[base] * scale;
        ks[n][d] = qkv[base + DIMC];
        vs[n][d] = qkv[base + 2 * DIMC];
    }
    __syncthreads();

    const int warp = tid >> 5, lane = tid & 31;
    const float* brow_base = biasx + (size_t)h * NTOK * NTOK;
    for (int n = warp; n < NTOK; n += 8) {
        const int m2 = lane + 32;
        float v1 = 0.f, v2 = 0.f;
        #pragma unroll
        for (int d = 0; d < HD; d++) {
            const float q = qs[n][d];
            v1 = fmaf(q, ks[lane][d], v1);
            if (m2 < NTOK) v2 = fmaf(q, ks[m2][d], v2);
        }
        const float* brow = brow_base + n * NTOK;
        v1 += brow[lane];
        v2 = (m2 < NTOK) ? v2 + brow[m2] : -CUDART_INF_F;
        float mx = fmaxf(v1, v2);
        #pragma unroll
        for (int o = 16; o; o >>= 1) mx = fmaxf(mx, __shfl_xor_sync(0xFFFFFFFFu, mx, o));
        float e1 = __expf(v1 - mx);
        float e2 = (m2 < NTOK) ? __expf(v2 - mx) : 0.f;
        float sm = e1 + e2;
        #pragma unroll
        for (int o = 16; o; o >>= 1) sm += __shfl_xor_sync(0xFFFFFFFFu, sm, o);
        const float inv = __frcp_rn(sm);
        at[n][lane] = e1 * inv;
        if (m2 < NTOK) at[n][m2] = e2 * inv;
    }
    __syncthreads();

    for (int idx = tid; idx < NTOK * HD; idx += 256) {
        const int n = idx >> 5, d = idx & 31;
        float s = 0.f;
        #pragma unroll
        for (int m = 0; m < NTOK; m++) s = fmaf(at[n][m], vs[m][d], s);
        outf[((size_t)b * NTOK + n) * DIMC + h * HD + d] = __float2half(s);
    }
}

// ---------------------------------------------------------------------------
extern "C" void kernel_launch(void* const* d_in, const int* in_sizes, int n_in,
                              void* d_out, int out_size)
{
    const float* x          = (const float*)d_in[0];
    const float* qkv_w      = (const float*)d_in[1];
    const float* qkv_b      = (const float*)d_in[2];
    const float* proj_w     = (const float*)d_in[3];
    const float* proj_b     = (const float*)d_in[4];
    const float* bias_table = (const float*)d_in[5];
    const int*   rpi        = (const int*)d_in[6];
    float* out = (float*)d_out;

    float *qkv, *biasx;
    __half *xf, *qwf, *af, *pwf;
    cudaGetSymbolAddress((void**)&qkv, g_qkv);
    cudaGetSymbolAddress((void**)&xf, g_xf);
    cudaGetSymbolAddress((void**)&qwf, g_qwf);
    cudaGetSymbolAddress((void**)&af, g_af);
    cudaGetSymbolAddress((void**)&pwf, g_pwf);
    cudaGetSymbolAddress((void**)&biasx, g_bias);

    cudaFuncSetAttribute(gemm_f16,
                         cudaFuncAttributeMaxDynamicSharedMemorySize, GEMM_SMEM_F16);

    // 0) conversions + bias expansion
    {
        size_t n4 = (size_t)MROWS * DIMC / 4;
        conv_f16<<<(unsigned)((n4 + 255) / 256), 256>>>(x, xf, n4);
        size_t w4 = (size_t)KDIM * QKV_N / 4;
        conv_f16<<<(unsigned)((w4 + 255) / 256), 256>>>(qkv_w, qwf, w4);
        size_t p4 = (size_t)KDIM * DIMC / 4;
        conv_f16<<<(unsigned)((p4 + 255) / 256), 256>>>(proj_w, pwf, p4);
        expand_bias<<<(NHEADS * NTOK * NTOK + 255) / 256, 256>>>(bias_table, rpi, biasx);
    }
    // 1) QKV GEMM (fp16)
    {
        dim3 grid(QKV_N / 128, MROWS / 128);
        gemm_f16<<<grid, 256, GEMM_SMEM_F16>>>(xf, qwf, qkv_b, qkv, MROWS, QKV_N);
    }
    // 2) Window attention (fp32 in, fp16 out)
    {
        dim3 grid(NWIN, NHEADS);
        win_attn<<<grid, 256>>>(qkv, biasx, af);
    }
    // 3) Proj GEMM (fp16)
    {
        dim3 grid(DIMC / 128, MROWS / 128);
        gemm_f16<<<grid, 256, GEMM_SMEM_F16>>>(af, pwf, proj_b, out, MROWS, DIMC);
    }
}